// round 3
// baseline (speedup 1.0000x reference)
#include <cuda_runtime.h>
#include <stdint.h>

#define Bn 16384
#define Tn 256
#define Dn 8
#define Fn 512
#define Cn 16
#define Ln 256

#define TTILES 16            // tree tiles (16 trees each)
#define BTILES 16            // sample tiles (1024 samples each)
#define BTILE  1024

// ---------------- device scratch (static, no runtime allocation) ------------
__device__ unsigned short g_fidx16[Tn * Dn];                 // 4 KB
__device__ unsigned char  g_dec[(size_t)Tn * Bn];            // 4 MB, layout [T][B]
__device__ float          g_part[(size_t)TTILES * Bn * Cn];  // 16 MB partials
__device__ int            g_cnt[BTILES];                     // completion counters

// ---------------- cp.async helpers ------------------------------------------
__device__ __forceinline__ void cp16(void* dst_smem, const void* src) {
    unsigned d = (unsigned)__cvta_generic_to_shared(dst_smem);
    asm volatile("cp.async.cg.shared.global [%0], [%1], 16;\n"
                 :: "r"(d), "l"(src));
}
__device__ __forceinline__ void cp4(void* dst_smem, const void* src) {
    unsigned d = (unsigned)__cvta_generic_to_shared(dst_smem);
    asm volatile("cp.async.ca.shared.global [%0], [%1], 4;\n"
                 :: "r"(d), "l"(src));
}
#define CP_COMMIT() asm volatile("cp.async.commit_group;\n" ::: "memory")
#define CP_WAIT1()  asm volatile("cp.async.wait_group 1;\n" ::: "memory")

// ---------------- kernel 1: argmax over F per (tree, depth) -----------------
__global__ void k_argmax(const float* __restrict__ fw) {
    if (blockIdx.x == 0 && threadIdx.x < BTILES) g_cnt[threadIdx.x] = 0;

    int g    = blockIdx.x * 8 + (threadIdx.x >> 5);   // 2048 warps total
    int lane = threadIdx.x & 31;
    const float* p = fw + (size_t)g * Fn;

    float best = -__int_as_float(0x7f800000);
    int   bi   = lane;
    bool  init = false;
    #pragma unroll
    for (int i = 0; i < Fn / 32; i++) {
        int   f = lane + (i << 5);
        float v = p[f];
        if (!init || v > best) { best = v; bi = f; init = true; }
    }
    #pragma unroll
    for (int off = 16; off; off >>= 1) {
        float ov = __shfl_down_sync(0xffffffffu, best, off);
        int   oi = __shfl_down_sync(0xffffffffu, bi,   off);
        if (ov > best || (ov == best && oi < bi)) { best = ov; bi = oi; }
    }
    if (lane == 0) g_fidx16[g] = (unsigned short)bi;
}

// ---------------- kernel 2: per-(sample,tree) decision byte -----------------
// block = 32 samples, 512 threads = 16 warps, each warp owns 16 trees.
// Only x is staged in smem (stride 513 -> conflict-free gathers); feature
// indices and thresholds are warp-uniform L1-hot global loads.
// smem = 64.1 KB -> 3 blocks/SM, 1.15 waves.
__global__ __launch_bounds__(512) void k_decide(const float* __restrict__ x,
                                                const float* __restrict__ thr) {
    extern __shared__ float s_x[];                     // 32 * 513 floats
    int tid = threadIdx.x;
    int b0  = blockIdx.x * 32;

    const float4* xg = (const float4*)x + (size_t)b0 * (Fn / 4);
    for (int i = tid; i < 32 * (Fn / 4); i += 512) {
        float4 v = xg[i];
        int row = i >> 7, c4 = i & 127;
        float* dst = s_x + row * 513 + c4 * 4;
        dst[0] = v.x; dst[1] = v.y; dst[2] = v.z; dst[3] = v.w;
    }
    __syncthreads();

    int warp = tid >> 5, lane = tid & 31;
    const float* xr = s_x + lane * 513;
    const uint4*  fpk = (const uint4*)g_fidx16;
    const float4* thv = (const float4*)thr;

    #pragma unroll 4
    for (int tt = 0; tt < 16; tt++) {
        int t = warp * 16 + tt;
        uint4  fp = __ldg(fpk + t);
        float4 t0 = __ldg(thv + t * 2);
        float4 t1 = __ldg(thv + t * 2 + 1);
        unsigned dec = 0;
        dec = (dec << 1) | (unsigned)(xr[fp.x & 0xFFFFu] > t0.x);
        dec = (dec << 1) | (unsigned)(xr[fp.x >> 16]     > t0.y);
        dec = (dec << 1) | (unsigned)(xr[fp.y & 0xFFFFu] > t0.z);
        dec = (dec << 1) | (unsigned)(xr[fp.y >> 16]     > t0.w);
        dec = (dec << 1) | (unsigned)(xr[fp.z & 0xFFFFu] > t1.x);
        dec = (dec << 1) | (unsigned)(xr[fp.z >> 16]     > t1.y);
        dec = (dec << 1) | (unsigned)(xr[fp.w & 0xFFFFu] > t1.z);
        dec = (dec << 1) | (unsigned)(xr[fp.w >> 16]     > t1.w);
        g_dec[(size_t)t * Bn + b0 + lane] = (unsigned char)dec;
    }
}

// ---------------- kernel 3: leaf gather + fused final reduction -------------
// grid (BTILES, TTILES). Block = 512 threads, 1024 samples, 16 trees.
// cp.async double-buffered response staging; leaf rows padded to 8 float4
// slots with (k + 5d) & 7 swizzle. Last block per b-tile (counter) sums the
// 16 partials in fixed tt order and writes d_out directly.
__global__ __launch_bounds__(512) void k_accum(const float* __restrict__ resp,
                                               float* __restrict__ out) {
    extern __shared__ float4 dynsmem[];
    float4*   s_r  = dynsmem;                            // 2 * Ln*8 float4
    unsigned* s_du = (unsigned*)(dynsmem + 2 * Ln * 8);  // 2 * 256 u32
    __shared__ int s_last;

    int tid   = threadIdx.x;
    int b0    = blockIdx.x * BTILE;
    int tbase = blockIdx.y * (Tn / TTILES);

    // async stage of tree (tbase+tt) into buffer buf
    auto stage = [&](int tt, int buf) {
        int t = tbase + tt;
        const float4* rs = (const float4*)resp + (size_t)t * (Ln * Cn / 4);
        #pragma unroll
        for (int j = 0; j < 2; j++) {
            int i = tid + j * 512;
            int d = i >> 2, k = i & 3;
            cp16(&s_r[buf * (Ln * 8) + d * 8 + ((k + 5 * d) & 7)], rs + i);
        }
        if (tid < BTILE / 4)
            cp4(&s_du[buf * (BTILE / 4) + tid],
                (const unsigned*)(g_dec + (size_t)t * Bn + b0) + tid);
    };

    stage(0, 0); CP_COMMIT();
    stage(1, 1); CP_COMMIT();

    float4 a[8];
    #pragma unroll
    for (int k = 0; k < 8; k++) a[k] = make_float4(0.f, 0.f, 0.f, 0.f);

    for (int tt = 0; tt < Tn / TTILES; tt++) {
        int buf = tt & 1;
        CP_WAIT1();            // tree tt resident (<=1 group in flight)
        __syncthreads();

        const unsigned char* sd =
            (const unsigned char*)(s_du + buf * (BTILE / 4));
        const float4* sr = s_r + buf * (Ln * 8);
        int d0 = sd[tid];
        int d1 = sd[tid + 512];
        const float4* r0 = sr + d0 * 8; int o0 = (5 * d0) & 7;
        const float4* r1 = sr + d1 * 8; int o1 = (5 * d1) & 7;
        #pragma unroll
        for (int k = 0; k < 4; k++) {
            float4 v0 = r0[(k + o0) & 7];
            a[k].x += v0.x; a[k].y += v0.y; a[k].z += v0.z; a[k].w += v0.w;
            float4 v1 = r1[(k + o1) & 7];
            a[4 + k].x += v1.x; a[4 + k].y += v1.y;
            a[4 + k].z += v1.z; a[4 + k].w += v1.w;
        }

        __syncthreads();       // all reads of buf done before restaging it
        if (tt + 2 < Tn / TTILES) stage(tt + 2, buf);
        CP_COMMIT();           // keep group count aligned even when empty
    }

    // write partial sums for this tree tile
    float4* p0 = (float4*)(g_part + ((size_t)blockIdx.y * Bn + b0 + tid) * Cn);
    float4* p1 = (float4*)(g_part + ((size_t)blockIdx.y * Bn + b0 + 512 + tid) * Cn);
    #pragma unroll
    for (int k = 0; k < 4; k++) { p0[k] = a[k]; p1[k] = a[4 + k]; }

    // last block for this b-tile performs the final reduction
    if (tid == 0) {
        __threadfence();
        int old = atomicAdd(&g_cnt[blockIdx.x], 1);
        s_last = (old == TTILES - 1) ? 1 : 0;
    }
    __syncthreads();
    if (s_last) {
        __threadfence();   // acquire: see all other blocks' partial writes
        for (int s = tid; s < BTILE; s += 512) {
            int b = b0 + s;
            float4 acc0 = make_float4(0.f, 0.f, 0.f, 0.f);
            float4 acc1 = acc0, acc2 = acc0, acc3 = acc0;
            #pragma unroll
            for (int tt = 0; tt < TTILES; tt++) {
                const float4* p =
                    (const float4*)(g_part + ((size_t)tt * Bn + b) * Cn);
                float4 v0 = p[0], v1 = p[1], v2 = p[2], v3 = p[3];
                acc0.x += v0.x; acc0.y += v0.y; acc0.z += v0.z; acc0.w += v0.w;
                acc1.x += v1.x; acc1.y += v1.y; acc1.z += v1.z; acc1.w += v1.w;
                acc2.x += v2.x; acc2.y += v2.y; acc2.z += v2.z; acc2.w += v2.w;
                acc3.x += v3.x; acc3.y += v3.y; acc3.z += v3.z; acc3.w += v3.w;
            }
            const float sc = 1.0f / (float)Tn;
            acc0.x *= sc; acc0.y *= sc; acc0.z *= sc; acc0.w *= sc;
            acc1.x *= sc; acc1.y *= sc; acc1.z *= sc; acc1.w *= sc;
            acc2.x *= sc; acc2.y *= sc; acc2.z *= sc; acc2.w *= sc;
            acc3.x *= sc; acc3.y *= sc; acc3.z *= sc; acc3.w *= sc;
            float4* o = (float4*)(out + (size_t)b * Cn);
            o[0] = acc0; o[1] = acc1; o[2] = acc2; o[3] = acc3;
        }
    }
}

// ---------------- launch -----------------------------------------------------
extern "C" void kernel_launch(void* const* d_in, const int* in_sizes, int n_in,
                              void* d_out, int out_size) {
    const float* x    = (const float*)d_in[0];   // (B, F)
    const float* fw   = (const float*)d_in[1];   // (T, D, F)
    const float* thr  = (const float*)d_in[2];   // (T, D)
    const float* resp = (const float*)d_in[3];   // (T, L, C)
    float* out = (float*)d_out;                  // (B, C)

    const int smem_dec = 32 * 513 * 4;                             // 65664 B
    const int smem_acc = 2 * Ln * 8 * 16 + 2 * (BTILE / 4) * 4;    // 67584 B
    cudaFuncSetAttribute(k_decide, cudaFuncAttributeMaxDynamicSharedMemorySize,
                         smem_dec);
    cudaFuncSetAttribute(k_accum, cudaFuncAttributeMaxDynamicSharedMemorySize,
                         smem_acc);
    (void)in_sizes; (void)n_in; (void)out_size;

    k_argmax<<<(Tn * Dn) / 8, 256>>>(fw);
    k_decide<<<Bn / 32, 512, smem_dec>>>(x, thr);
    k_accum<<<dim3(BTILES, TTILES), 512, smem_acc>>>(resp, out);
}

// round 4
// speedup vs baseline: 1.2946x; 1.2946x over previous
#include <cuda_runtime.h>
#include <stdint.h>

#define Bn 16384
#define Tn 256
#define Dn 8
#define Fn 512
#define Cn 16
#define Ln 256

#define TTILES 16            // tree tiles (16 trees each)
#define BTILES 16            // sample tiles (1024 samples each)
#define BTILE  1024

// ---------------- device scratch (static, no runtime allocation) ------------
__device__ unsigned short g_fidx16[Tn * Dn];                 // 4 KB
__device__ unsigned char  g_dec[(size_t)Tn * Bn];            // 4 MB, layout [T][B]
__device__ float          g_part[(size_t)TTILES * Bn * Cn];  // 16 MB partials

// ---------------- kernel 1: argmax over F per (tree, depth) -----------------
// one warp per (t,d). All 16 strided loads issued before any compare so the
// full 64 B/lane is in flight (round-3 profile: regs=30 capped MLP, 820 GB/s).
__global__ void k_argmax(const float* __restrict__ fw) {
    int g    = blockIdx.x * 8 + (threadIdx.x >> 5);   // 2048 warps total
    int lane = threadIdx.x & 31;
    const float* p = fw + (size_t)g * Fn;

    float v[16];
    #pragma unroll
    for (int i = 0; i < 16; i++) v[i] = p[lane + (i << 5)];

    float best = v[0];
    int   bi   = lane;
    #pragma unroll
    for (int i = 1; i < 16; i++)
        if (v[i] > best) { best = v[i]; bi = lane + (i << 5); }

    #pragma unroll
    for (int off = 16; off; off >>= 1) {
        float ov = __shfl_down_sync(0xffffffffu, best, off);
        int   oi = __shfl_down_sync(0xffffffffu, bi,   off);
        if (ov > best || (ov == best && oi < bi)) { best = ov; bi = oi; }
    }
    if (lane == 0) g_fidx16[g] = (unsigned short)bi;
}

// ---------------- kernel 2: per-(sample,tree) decision byte -----------------
// 256 blocks (exactly one wave at 2 blocks/SM), each handles 2 groups of 32
// samples. 512 threads = 16 warps; each warp owns 16 trees. x rows in smem
// with stride 513 -> conflict-free gathers. fidx/thr staged once per block.
__global__ __launch_bounds__(512) void k_decide(const float* __restrict__ x,
                                                const float* __restrict__ thr) {
    extern __shared__ float smem[];
    float* s_x   = smem;                                   // 32 * 513 floats
    uint4* s_fpk = (uint4*)(smem + 32 * 513);              // 256 * 16 B
    float* s_thr = (float*)(s_fpk + Tn);                   // 2048 floats

    int tid  = threadIdx.x;
    int warp = tid >> 5, lane = tid & 31;
    int b00  = blockIdx.x * 64;

    for (int i = tid; i < (Tn * Dn) / 2; i += 512)
        ((unsigned*)s_fpk)[i] = ((const unsigned*)g_fidx16)[i];
    for (int i = tid; i < Tn * Dn; i += 512)
        s_thr[i] = thr[i];

    #pragma unroll
    for (int grp = 0; grp < 2; grp++) {
        int b0 = b00 + grp * 32;
        if (grp) __syncthreads();   // prior compute done before restaging x
        const float4* xg = (const float4*)x + (size_t)b0 * (Fn / 4);
        for (int i = tid; i < 32 * (Fn / 4); i += 512) {
            float4 v = xg[i];
            int row = i >> 7, c4 = i & 127;
            float* dst = s_x + row * 513 + c4 * 4;
            dst[0] = v.x; dst[1] = v.y; dst[2] = v.z; dst[3] = v.w;
        }
        __syncthreads();

        const float* xr = s_x + lane * 513;
        #pragma unroll 4
        for (int tt = 0; tt < 16; tt++) {
            int t = warp * 16 + tt;
            uint4 fp = s_fpk[t];
            const float4* th = (const float4*)(s_thr + t * 8);
            float4 t0 = th[0], t1 = th[1];
            unsigned dec = 0;
            dec = (dec << 1) | (unsigned)(xr[fp.x & 0xFFFFu] > t0.x);
            dec = (dec << 1) | (unsigned)(xr[fp.x >> 16]     > t0.y);
            dec = (dec << 1) | (unsigned)(xr[fp.y & 0xFFFFu] > t0.z);
            dec = (dec << 1) | (unsigned)(xr[fp.y >> 16]     > t0.w);
            dec = (dec << 1) | (unsigned)(xr[fp.z & 0xFFFFu] > t1.x);
            dec = (dec << 1) | (unsigned)(xr[fp.z >> 16]     > t1.y);
            dec = (dec << 1) | (unsigned)(xr[fp.w & 0xFFFFu] > t1.z);
            dec = (dec << 1) | (unsigned)(xr[fp.w >> 16]     > t1.w);
            g_dec[(size_t)t * Bn + b0 + lane] = (unsigned char)dec;
        }
    }
}

// ---------------- kernel 3: leaf gather, double-buffered staging ------------
// (round-2 version verbatim — known good)
__global__ __launch_bounds__(512) void k_accum(const float* __restrict__ resp) {
    extern __shared__ float4 dynsmem[];
    float4*   s_r  = dynsmem;                            // 2 * Ln*8 float4
    unsigned* s_du = (unsigned*)(dynsmem + 2 * Ln * 8);  // 2 * 256 u32

    int tid   = threadIdx.x;
    int b0    = blockIdx.x * BTILE;
    int tbase = blockIdx.y * (Tn / TTILES);

    float4 a[8];
    #pragma unroll
    for (int k = 0; k < 8; k++) a[k] = make_float4(0.f, 0.f, 0.f, 0.f);

    {
        const float4* rs = (const float4*)resp + (size_t)tbase * (Ln * Cn / 4);
        #pragma unroll
        for (int j = 0; j < 2; j++) {
            int i = tid + j * 512;
            float4 v = rs[i];
            int d = i >> 2, k = i & 3;
            s_r[d * 8 + ((k + 5 * d) & 7)] = v;
        }
        if (tid < BTILE / 4)
            s_du[tid] = ((const unsigned*)(g_dec + (size_t)tbase * Bn + b0))[tid];
    }
    __syncthreads();

    for (int tt = 0; tt < Tn / TTILES; tt++) {
        int cur = tt & 1;
        float4 nv0, nv1; unsigned ndu = 0;
        bool have = (tt + 1 < Tn / TTILES);
        if (have) {
            int t = tbase + tt + 1;
            const float4* rs = (const float4*)resp + (size_t)t * (Ln * Cn / 4);
            nv0 = rs[tid];
            nv1 = rs[tid + 512];
            if (tid < BTILE / 4)
                ndu = ((const unsigned*)(g_dec + (size_t)t * Bn + b0))[tid];
        }

        const unsigned char* sd = (const unsigned char*)(s_du + cur * (BTILE / 4));
        const float4* sr = s_r + cur * (Ln * 8);
        int d0 = sd[tid];
        int d1 = sd[tid + 512];
        const float4* r0 = sr + d0 * 8; int o0 = (5 * d0) & 7;
        const float4* r1 = sr + d1 * 8; int o1 = (5 * d1) & 7;
        #pragma unroll
        for (int k = 0; k < 4; k++) {
            float4 v0 = r0[(k + o0) & 7];
            a[k].x += v0.x; a[k].y += v0.y; a[k].z += v0.z; a[k].w += v0.w;
            float4 v1 = r1[(k + o1) & 7];
            a[4 + k].x += v1.x; a[4 + k].y += v1.y;
            a[4 + k].z += v1.z; a[4 + k].w += v1.w;
        }

        if (have) {
            int nb = cur ^ 1;
            float4* dr = s_r + nb * (Ln * 8);
            { int i = tid;       int d = i >> 2, k = i & 3; dr[d * 8 + ((k + 5 * d) & 7)] = nv0; }
            { int i = tid + 512; int d = i >> 2, k = i & 3; dr[d * 8 + ((k + 5 * d) & 7)] = nv1; }
            if (tid < BTILE / 4) s_du[nb * (BTILE / 4) + tid] = ndu;
        }
        __syncthreads();
    }

    float4* p0 = (float4*)(g_part + ((size_t)blockIdx.y * Bn + b0 + tid) * Cn);
    float4* p1 = (float4*)(g_part + ((size_t)blockIdx.y * Bn + b0 + 512 + tid) * Cn);
    #pragma unroll
    for (int k = 0; k < 4; k++) { p0[k] = a[k]; p1[k] = a[4 + k]; }
}

// ---------------- kernel 4: reduce partials across tree tiles ---------------
// float2 lanes with an explicit 16-element register batch: all 16 loads in
// flight before any add (round-2 profile: regs=32 capped MLP at ~8).
__global__ __launch_bounds__(256) void k_reduce(float* __restrict__ out) {
    int i = blockIdx.x * 256 + threadIdx.x;       // 0 .. Bn*Cn/2-1
    const float2* p = (const float2*)g_part;

    float2 v[16];
    #pragma unroll
    for (int tt = 0; tt < TTILES; tt++)
        v[tt] = p[(size_t)tt * (Bn * Cn / 2) + i];

    float sx = 0.f, sy = 0.f;
    #pragma unroll
    for (int tt = 0; tt < TTILES; tt++) { sx += v[tt].x; sy += v[tt].y; }

    const float sc = 1.0f / (float)Tn;
    ((float2*)out)[i] = make_float2(sx * sc, sy * sc);
}

// ---------------- launch -----------------------------------------------------
extern "C" void kernel_launch(void* const* d_in, const int* in_sizes, int n_in,
                              void* d_out, int out_size) {
    const float* x    = (const float*)d_in[0];   // (B, F)
    const float* fw   = (const float*)d_in[1];   // (T, D, F)
    const float* thr  = (const float*)d_in[2];   // (T, D)
    const float* resp = (const float*)d_in[3];   // (T, L, C)
    float* out = (float*)d_out;                  // (B, C)

    const int smem_dec = 32 * 513 * 4 + Tn * 16 + Tn * Dn * 4;     // 77952 B
    const int smem_acc = 2 * Ln * 8 * 16 + 2 * (BTILE / 4) * 4;    // 67584 B
    cudaFuncSetAttribute(k_decide, cudaFuncAttributeMaxDynamicSharedMemorySize,
                         smem_dec);
    cudaFuncSetAttribute(k_accum, cudaFuncAttributeMaxDynamicSharedMemorySize,
                         smem_acc);
    (void)in_sizes; (void)n_in; (void)out_size;

    k_argmax<<<(Tn * Dn) / 8, 256>>>(fw);
    k_decide<<<Bn / 64, 512, smem_dec>>>(x, thr);
    k_accum<<<dim3(BTILES, TTILES), 512, smem_acc>>>(resp);
    k_reduce<<<(Bn * Cn / 2) / 256, 256>>>(out);
}